// round 10
// baseline (speedup 1.0000x reference)
#include <cuda_runtime.h>

// S5 associative scan: (A_i,Bu_i)*(A_j,Bu_j) = (A_j*A_i, A_j*Bu_i + Bu_j)
// Per channel d:  cumA_t = A_t * cumA_{t-1},   S_t = A_t*S_{t-1} + Bu_t
// out[0:T*D] = A_scan, out[T*D:2*T*D] = Bu_scan.
//
// 3-pass chunked scan, float4-vectorized, 4 chunks per 256-thread block.
// GG=8192 chunks -> 2048 blocks in passes 1/3 (finer wave granularity, higher
// occupancy vs 1024). L2 carry-over: pass1 reads default-cached (tail of
// inputs stays L2-resident), pass3 walks chunks in REVERSE order to hit those
// lines, pass3 outputs use streaming stores (.cs) so they don't evict inputs.

#define TT 131072
#define DD 256
#define GG 8192              // time chunks
#define LL (TT / GG)         // 16 rows per chunk
#define V4 (DD / 4)          // 64 float4 per row
#define CPB 4                // chunks per block (passes 1 & 3)
#define P2T 1024             // threads in pass2
#define SER (GG / P2T)       // 8 chunks combined serially per pass2 thread

// Scratch (static device arrays — allocation rules).
__device__ float g_aggA[GG * DD];    // [c][d] chunk-major
__device__ float g_aggS[GG * DD];
__device__ float g_prefA[GG * DD];   // [c][d] chunk-major (exclusive prefix)
__device__ float g_prefS[GG * DD];

// ---------------- pass 1: per-chunk aggregates ----------------
__global__ __launch_bounds__(V4 * CPB, 6) void s5_pass1(const float4* __restrict__ A4,
                                                        const float4* __restrict__ Bu4) {
    const int sub = threadIdx.x >> 6;       // chunk within block
    const int t   = threadIdx.x & 63;       // float4 lane (channels 4t..4t+3)
    const int c   = blockIdx.x * CPB + sub;
    const size_t base = (size_t)c * LL * V4 + t;

    float4 aA = make_float4(1.f, 1.f, 1.f, 1.f);
    float4 s  = make_float4(0.f, 0.f, 0.f, 0.f);
#pragma unroll
    for (int i = 0; i < LL; ++i) {
        const float4 a  = A4[base + (size_t)i * V4];    // default caching: seed L2
        const float4 bu = Bu4[base + (size_t)i * V4];
        aA.x *= a.x; aA.y *= a.y; aA.z *= a.z; aA.w *= a.w;
        s.x = fmaf(a.x, s.x, bu.x);
        s.y = fmaf(a.y, s.y, bu.y);
        s.z = fmaf(a.z, s.z, bu.z);
        s.w = fmaf(a.w, s.w, bu.w);
    }
    ((float4*)g_aggA)[c * V4 + t] = aA;     // coalesced, stays in L2 for pass2
    ((float4*)g_aggS)[c * V4 + t] = s;
}

// ---------------- pass 2: cross-chunk scan (one block per channel) ----------
__global__ __launch_bounds__(P2T) void s5_pass2() {
    __shared__ float shA[P2T];
    __shared__ float shS[P2T];
    const int d = blockIdx.x;
    const int c = threadIdx.x;              // owns chunks SER*c .. SER*c+SER-1

    // serial combine of SER consecutive chunk aggregates (keep raw copies)
    float la[SER], ls[SER];
    float vA = 1.f, vS = 0.f;
#pragma unroll
    for (int j = 0; j < SER; ++j) {
        const float a = g_aggA[(c * SER + j) * DD + d];
        const float s = g_aggS[(c * SER + j) * DD + d];
        la[j] = a; ls[j] = s;
        vS = fmaf(a, vS, s);
        vA = vA * a;
    }
    shA[c] = vA;
    shS[c] = vS;
    __syncthreads();

    // Kogge-Stone inclusive scan over 1024 thread-aggregates
#pragma unroll
    for (int off = 1; off < P2T; off <<= 1) {
        float pA = 0.f, pS = 0.f;
        const bool valid = (c >= off);
        if (valid) { pA = shA[c - off]; pS = shS[c - off]; }
        __syncthreads();
        if (valid) {
            vS = fmaf(vA, pS, vS);
            vA = vA * pA;
            shA[c] = vA;
            shS[c] = vS;
        }
        __syncthreads();
    }

    // exclusive prefix entering this thread's SER chunks
    float eA = (c == 0) ? 1.f : shA[c - 1];
    float eS = (c == 0) ? 0.f : shS[c - 1];
#pragma unroll
    for (int j = 0; j < SER; ++j) {
        g_prefA[(c * SER + j) * DD + d] = eA;
        g_prefS[(c * SER + j) * DD + d] = eS;
        eS = fmaf(la[j], eS, ls[j]);
        eA = eA * la[j];
    }
}

// ---------------- pass 3: rescan with prefix, write outputs -----------------
// Chunks processed in REVERSE order: first pass3 blocks read the input lines
// pass1 touched last (still L2-resident).
__global__ __launch_bounds__(V4 * CPB, 6) void s5_pass3(const float4* __restrict__ A4,
                                                        const float4* __restrict__ Bu4,
                                                        float4* __restrict__ outA4,
                                                        float4* __restrict__ outS4) {
    const int sub = threadIdx.x >> 6;
    const int t   = threadIdx.x & 63;
    const int c   = (GG - 1) - (blockIdx.x * CPB + sub);   // reverse mapping
    const size_t base = (size_t)c * LL * V4 + t;

    float4 aA = ((const float4*)g_prefA)[c * V4 + t];   // coalesced (L2 hit)
    float4 s  = ((const float4*)g_prefS)[c * V4 + t];

#pragma unroll
    for (int i = 0; i < LL; ++i) {
        const size_t idx = base + (size_t)i * V4;
        const float4 a  = A4[idx];          // default caching: exploit L2 leftovers
        const float4 bu = Bu4[idx];
        aA.x *= a.x; aA.y *= a.y; aA.z *= a.z; aA.w *= a.w;
        s.x = fmaf(a.x, s.x, bu.x);
        s.y = fmaf(a.y, s.y, bu.y);
        s.z = fmaf(a.z, s.z, bu.z);
        s.w = fmaf(a.w, s.w, bu.w);
        __stcs(outA4 + idx, aA);            // streaming: don't evict inputs
        __stcs(outS4 + idx, s);
    }
}

extern "C" void kernel_launch(void* const* d_in, const int* in_sizes, int n_in,
                              void* d_out, int out_size) {
    const float4* A4  = (const float4*)d_in[0];
    const float4* Bu4 = (const float4*)d_in[1];
    float4* outA4 = (float4*)d_out;
    float4* outS4 = (float4*)((float*)d_out + (size_t)TT * DD);

    s5_pass1<<<GG / CPB, V4 * CPB>>>(A4, Bu4);
    s5_pass2<<<DD, P2T>>>();
    s5_pass3<<<GG / CPB, V4 * CPB>>>(A4, Bu4, outA4, outS4);
}

// round 11
// speedup vs baseline: 1.0756x; 1.0756x over previous
#include <cuda_runtime.h>

// S5 associative scan: (A_i,Bu_i)*(A_j,Bu_j) = (A_j*A_i, A_j*Bu_i + Bu_j)
// Per channel d:  cumA_t = A_t * cumA_{t-1},   S_t = A_t*S_{t-1} + Bu_t
// out[0:T*D] = A_scan, out[T*D:2*T*D] = Bu_scan.
//
// 3-pass chunked scan, float4-vectorized, 4 chunks per 256-thread block.
// GG=8192 -> 2048 blocks in passes 1/3 (fine wave granularity, 67%+ occ).
// L2 carry-over: pass1 reads default-cached, pass3 walks chunks in REVERSE,
// pass3 outputs stream (.cs). Pass2 is a tiled 3-phase scan with fully
// coalesced scratch access (sector-waste-free), unlike the strided version.

#define TT 131072
#define DD 256
#define GG 8192              // time chunks
#define LL (TT / GG)         // 16 rows per chunk
#define V4 (DD / 4)          // 64 float4 per row
#define CPB 4                // chunks per block (passes 1 & 3)

// pass2 tiling: 32 blocks x 1024 threads; 8 channels/block, 128 chunk-groups,
// 64 chunks combined serially per thread.
#define P2_CH   8
#define P2_CG   128
#define P2_SER  (GG / P2_CG)          // 64
#define P2_GRID (DD / P2_CH)          // 32

// Scratch (static device arrays — allocation rules).
__device__ float g_aggA[GG * DD];    // [c][d] chunk-major
__device__ float g_aggS[GG * DD];
__device__ float g_prefA[GG * DD];   // [c][d] chunk-major (exclusive prefix)
__device__ float g_prefS[GG * DD];

// ---------------- pass 1: per-chunk aggregates ----------------
__global__ __launch_bounds__(V4 * CPB, 6) void s5_pass1(const float4* __restrict__ A4,
                                                        const float4* __restrict__ Bu4) {
    const int sub = threadIdx.x >> 6;       // chunk within block
    const int t   = threadIdx.x & 63;       // float4 lane (channels 4t..4t+3)
    const int c   = blockIdx.x * CPB + sub;
    const size_t base = (size_t)c * LL * V4 + t;

    float4 aA = make_float4(1.f, 1.f, 1.f, 1.f);
    float4 s  = make_float4(0.f, 0.f, 0.f, 0.f);
#pragma unroll
    for (int i = 0; i < LL; ++i) {
        const float4 a  = A4[base + (size_t)i * V4];    // default caching: seed L2
        const float4 bu = Bu4[base + (size_t)i * V4];
        aA.x *= a.x; aA.y *= a.y; aA.z *= a.z; aA.w *= a.w;
        s.x = fmaf(a.x, s.x, bu.x);
        s.y = fmaf(a.y, s.y, bu.y);
        s.z = fmaf(a.z, s.z, bu.z);
        s.w = fmaf(a.w, s.w, bu.w);
    }
    ((float4*)g_aggA)[c * V4 + t] = aA;     // coalesced, mostly L2-resident for pass2
    ((float4*)g_aggS)[c * V4 + t] = s;
}

// ---------------- pass 2: cross-chunk scan, tiled + coalesced ----------------
// Block = 8 channels x 128 chunk-groups. Warp loads span 8 consecutive
// channels x 4 chunk rows -> 4 full 32B sectors, no waste.
__global__ __launch_bounds__(P2_CG * P2_CH) void s5_pass2() {
    __shared__ float shA[P2_CG * P2_CH];
    __shared__ float shS[P2_CG * P2_CH];
    const int dl = threadIdx.x & (P2_CH - 1);   // channel lane 0..7
    const int cg = threadIdx.x / P2_CH;         // chunk group 0..127
    const int d  = blockIdx.x * P2_CH + dl;     // global channel
    const int c0 = cg * P2_SER;                 // first chunk of this group

    // Phase A: serial combine of 64 consecutive chunk aggregates
    float vA = 1.f, vS = 0.f;
#pragma unroll 8
    for (int j = 0; j < P2_SER; ++j) {
        const int idx = (c0 + j) * DD + d;
        const float a = g_aggA[idx];
        const float s = g_aggS[idx];
        vS = fmaf(a, vS, s);
        vA = vA * a;
    }
    shA[cg * P2_CH + dl] = vA;
    shS[cg * P2_CH + dl] = vS;
    __syncthreads();

    // Phase B: Kogge-Stone over 128 chunk-groups (per channel lane)
#pragma unroll
    for (int off = 1; off < P2_CG; off <<= 1) {
        float pA = 0.f, pS = 0.f;
        const bool valid = (cg >= off);
        if (valid) {
            pA = shA[(cg - off) * P2_CH + dl];
            pS = shS[(cg - off) * P2_CH + dl];
        }
        __syncthreads();
        if (valid) {
            vS = fmaf(vA, pS, vS);
            vA = vA * pA;
            shA[cg * P2_CH + dl] = vA;
            shS[cg * P2_CH + dl] = vS;
        }
        __syncthreads();
    }

    // Phase C: re-walk chunks, emit exclusive prefixes (coalesced, L2 hits)
    float eA = (cg == 0) ? 1.f : shA[(cg - 1) * P2_CH + dl];
    float eS = (cg == 0) ? 0.f : shS[(cg - 1) * P2_CH + dl];
#pragma unroll 4
    for (int j = 0; j < P2_SER; ++j) {
        const int idx = (c0 + j) * DD + d;
        g_prefA[idx] = eA;
        g_prefS[idx] = eS;
        const float a = g_aggA[idx];
        const float s = g_aggS[idx];
        eS = fmaf(a, eS, s);
        eA = eA * a;
    }
}

// ---------------- pass 3: rescan with prefix, write outputs -----------------
// Chunks processed in REVERSE order: first pass3 blocks read the input lines
// pass1 touched last (still L2-resident).
__global__ __launch_bounds__(V4 * CPB, 6) void s5_pass3(const float4* __restrict__ A4,
                                                        const float4* __restrict__ Bu4,
                                                        float4* __restrict__ outA4,
                                                        float4* __restrict__ outS4) {
    const int sub = threadIdx.x >> 6;
    const int t   = threadIdx.x & 63;
    const int c   = (GG - 1) - (blockIdx.x * CPB + sub);   // reverse mapping
    const size_t base = (size_t)c * LL * V4 + t;

    float4 aA = ((const float4*)g_prefA)[c * V4 + t];   // coalesced (L2 hit)
    float4 s  = ((const float4*)g_prefS)[c * V4 + t];

#pragma unroll
    for (int i = 0; i < LL; ++i) {
        const size_t idx = base + (size_t)i * V4;
        const float4 a  = A4[idx];          // default caching: exploit L2 leftovers
        const float4 bu = Bu4[idx];
        aA.x *= a.x; aA.y *= a.y; aA.z *= a.z; aA.w *= a.w;
        s.x = fmaf(a.x, s.x, bu.x);
        s.y = fmaf(a.y, s.y, bu.y);
        s.z = fmaf(a.z, s.z, bu.z);
        s.w = fmaf(a.w, s.w, bu.w);
        __stcs(outA4 + idx, aA);            // streaming: don't evict inputs
        __stcs(outS4 + idx, s);
    }
}

extern "C" void kernel_launch(void* const* d_in, const int* in_sizes, int n_in,
                              void* d_out, int out_size) {
    const float4* A4  = (const float4*)d_in[0];
    const float4* Bu4 = (const float4*)d_in[1];
    float4* outA4 = (float4*)d_out;
    float4* outS4 = (float4*)((float*)d_out + (size_t)TT * DD);

    s5_pass1<<<GG / CPB, V4 * CPB>>>(A4, Bu4);
    s5_pass2<<<P2_GRID, P2_CG * P2_CH>>>();
    s5_pass3<<<GG / CPB, V4 * CPB>>>(A4, Bu4, outA4, outS4);
}

// round 13
// speedup vs baseline: 1.0981x; 1.0209x over previous
#include <cuda_runtime.h>

// S5 associative scan: (A_i,Bu_i)*(A_j,Bu_j) = (A_j*A_i, A_j*Bu_i + Bu_j)
// Per channel d:  cumA_t = A_t * cumA_{t-1},   S_t = A_t*S_{t-1} + Bu_t
// out[0:T*D] = A_scan, out[T*D:2*T*D] = Bu_scan.
//
// 3-pass chunked scan combining the measured-best variant of each pass:
//   pass1: GG=8192 fine chunks (2048 blocks, best occ/DRAM%), pair-combines
//          in smem and emits COARSE GG2=4096 aggregates (coalesced float4).
//   pass2: strided per-channel scan over 4096 coarse chunks, 256 blocks x
//          1024 threads (full-chip parallelism hides sector amplification).
//   pass3: coarse chunks (32-row bursts -> fewer DRAM read/write turnarounds),
//          2048 blocks x 128 threads for fine wave granularity; REVERSE chunk
//          order to hit pass1's L2 leftovers; streaming (.cs) output stores.

#define TT 131072
#define DD 256
#define V4 (DD / 4)          // 64 float4 per row

#define G1 8192              // pass1 fine chunks
#define L1 (TT / G1)         // 16 rows per fine chunk
#define CPB1 4               // fine chunks per pass1 block

#define G2 4096              // coarse chunks (pass2/pass3 granularity)
#define L2R (TT / G2)        // 32 rows per coarse chunk
#define P2T 1024             // pass2 threads per block
#define SER2 (G2 / P2T)      // 4 coarse chunks serially per pass2 thread

#define CPB3 2               // coarse chunks per pass3 block (128 threads)

// Scratch (static device arrays — allocation rules). 16MB total, L2-resident.
__device__ float g_aggA[G2 * DD];    // [c2][d] chunk-major coarse aggregates
__device__ float g_aggS[G2 * DD];
__device__ float g_prefA[G2 * DD];   // [c2][d] exclusive prefixes
__device__ float g_prefS[G2 * DD];

// ---------------- pass 1: fine scan -> coarse aggregates ----------------
__global__ __launch_bounds__(V4 * CPB1, 6) void s5_pass1(const float4* __restrict__ A4,
                                                         const float4* __restrict__ Bu4) {
    __shared__ float4 shA[2][V4];
    __shared__ float4 shS[2][V4];

    const int sub = threadIdx.x >> 6;       // fine chunk within block (0..3)
    const int t   = threadIdx.x & 63;       // float4 lane (channels 4t..4t+3)
    const int c   = blockIdx.x * CPB1 + sub;
    const size_t base = (size_t)c * L1 * V4 + t;

    float4 aA = make_float4(1.f, 1.f, 1.f, 1.f);
    float4 s  = make_float4(0.f, 0.f, 0.f, 0.f);
#pragma unroll
    for (int i = 0; i < L1; ++i) {
        const float4 a  = A4[base + (size_t)i * V4];    // default caching: seed L2
        const float4 bu = Bu4[base + (size_t)i * V4];
        aA.x *= a.x; aA.y *= a.y; aA.z *= a.z; aA.w *= a.w;
        s.x = fmaf(a.x, s.x, bu.x);
        s.y = fmaf(a.y, s.y, bu.y);
        s.z = fmaf(a.z, s.z, bu.z);
        s.w = fmaf(a.w, s.w, bu.w);
    }

    // pair-combine fine chunks (sub0,sub1)->coarse0, (sub2,sub3)->coarse1
    if (sub & 1) {                          // odd sub = LATER fine chunk
        shA[sub >> 1][t] = aA;
        shS[sub >> 1][t] = s;
    }
    __syncthreads();
    if (!(sub & 1)) {                       // even sub = EARLIER fine chunk
        const float4 a1 = shA[sub >> 1][t];
        const float4 s1 = shS[sub >> 1][t];
        float4 cA, cS;                      // coarse = later(a1,s1) ∘ earlier(aA,s)
        cA.x = a1.x * aA.x; cA.y = a1.y * aA.y;
        cA.z = a1.z * aA.z; cA.w = a1.w * aA.w;
        cS.x = fmaf(a1.x, s.x, s1.x); cS.y = fmaf(a1.y, s.y, s1.y);
        cS.z = fmaf(a1.z, s.z, s1.z); cS.w = fmaf(a1.w, s.w, s1.w);
        const int c2 = blockIdx.x * 2 + (sub >> 1);
        ((float4*)g_aggA)[c2 * V4 + t] = cA;    // coalesced, stays in L2
        ((float4*)g_aggS)[c2 * V4 + t] = cS;
    }
}

// ---------------- pass 2: cross-chunk scan (one block per channel) ----------
__global__ __launch_bounds__(P2T) void s5_pass2() {
    __shared__ float shA[P2T];
    __shared__ float shS[P2T];
    const int d = blockIdx.x;
    const int c = threadIdx.x;              // owns coarse chunks 4c..4c+3

    float la[SER2], ls[SER2];
    float vA = 1.f, vS = 0.f;
#pragma unroll
    for (int j = 0; j < SER2; ++j) {
        const float a = g_aggA[(c * SER2 + j) * DD + d];
        const float s = g_aggS[(c * SER2 + j) * DD + d];
        la[j] = a; ls[j] = s;
        vS = fmaf(a, vS, s);
        vA = vA * a;
    }
    shA[c] = vA;
    shS[c] = vS;
    __syncthreads();

    // Kogge-Stone inclusive scan over 1024 thread-aggregates
#pragma unroll
    for (int off = 1; off < P2T; off <<= 1) {
        float pA = 0.f, pS = 0.f;
        const bool valid = (c >= off);
        if (valid) { pA = shA[c - off]; pS = shS[c - off]; }
        __syncthreads();
        if (valid) {
            vS = fmaf(vA, pS, vS);
            vA = vA * pA;
            shA[c] = vA;
            shS[c] = vS;
        }
        __syncthreads();
    }

    // exclusive prefix entering this thread's SER2 chunks
    float eA = (c == 0) ? 1.f : shA[c - 1];
    float eS = (c == 0) ? 0.f : shS[c - 1];
#pragma unroll
    for (int j = 0; j < SER2; ++j) {
        g_prefA[(c * SER2 + j) * DD + d] = eA;
        g_prefS[(c * SER2 + j) * DD + d] = eS;
        eS = fmaf(la[j], eS, ls[j]);
        eA = eA * la[j];
    }
}

// ---------------- pass 3: rescan coarse chunks, write outputs ---------------
// 128-thread blocks (2 coarse chunks each) for fine wave granularity; 32-row
// bursts per thread; REVERSE order to hit pass1's L2-resident input tail.
__global__ __launch_bounds__(V4 * CPB3, 12) void s5_pass3(const float4* __restrict__ A4,
                                                          const float4* __restrict__ Bu4,
                                                          float4* __restrict__ outA4,
                                                          float4* __restrict__ outS4) {
    const int sub = threadIdx.x >> 6;       // coarse chunk within block (0..1)
    const int t   = threadIdx.x & 63;
    const int c2  = (G2 - 1) - (blockIdx.x * CPB3 + sub);   // reverse mapping
    const size_t base = (size_t)c2 * L2R * V4 + t;

    float4 aA = ((const float4*)g_prefA)[c2 * V4 + t];   // coalesced (L2 hit)
    float4 s  = ((const float4*)g_prefS)[c2 * V4 + t];

#pragma unroll
    for (int i = 0; i < L2R; ++i) {
        const size_t idx = base + (size_t)i * V4;
        const float4 a  = A4[idx];          // default caching: exploit L2 leftovers
        const float4 bu = Bu4[idx];
        aA.x *= a.x; aA.y *= a.y; aA.z *= a.z; aA.w *= a.w;
        s.x = fmaf(a.x, s.x, bu.x);
        s.y = fmaf(a.y, s.y, bu.y);
        s.z = fmaf(a.z, s.z, bu.z);
        s.w = fmaf(a.w, s.w, bu.w);
        __stcs(outA4 + idx, aA);            // streaming: don't evict inputs
        __stcs(outS4 + idx, s);
    }
}

extern "C" void kernel_launch(void* const* d_in, const int* in_sizes, int n_in,
                              void* d_out, int out_size) {
    const float4* A4  = (const float4*)d_in[0];
    const float4* Bu4 = (const float4*)d_in[1];
    float4* outA4 = (float4*)d_out;
    float4* outS4 = (float4*)((float*)d_out + (size_t)TT * DD);

    s5_pass1<<<G1 / CPB1, V4 * CPB1>>>(A4, Bu4);
    s5_pass2<<<DD, P2T>>>();
    s5_pass3<<<G2 / CPB3, V4 * CPB3>>>(A4, Bu4, outA4, outS4);
}

// round 14
// speedup vs baseline: 1.1211x; 1.0209x over previous
#include <cuda_runtime.h>

// S5 associative scan: (A_i,Bu_i)*(A_j,Bu_j) = (A_j*A_i, A_j*Bu_i + Bu_j)
// Per channel d:  cumA_t = A_t * cumA_{t-1},   S_t = A_t*S_{t-1} + Bu_t
// out[0:T*D] = A_scan, out[T*D:2*T*D] = Bu_scan.
//
// Measured-best assembly (R9/R11/R13 components):
//   pass1: 2048 blocks x 256 thr, 16-row fine chunks (best occ/DRAM%), fused
//          smem pair-combine -> 4096 coarse aggregates (coalesced float4).
//   pass2: strided per-channel scan over 4096 coarse chunks, 256 blocks x
//          1024 threads (full-chip parallelism hides sector amplification).
//   pass3: 1024 blocks x 256 thr (4 coarse chunks/block), 32-row bursts,
//          REVERSE chunk order to hit pass1's L2-resident input tail,
//          streaming (.cs) output stores so outputs don't evict inputs.

#define TT 131072
#define DD 256
#define V4 (DD / 4)          // 64 float4 per row

#define G1 8192              // pass1 fine chunks
#define L1 (TT / G1)         // 16 rows per fine chunk
#define CPB1 4               // fine chunks per pass1 block

#define G2 4096              // coarse chunks (pass2/pass3 granularity)
#define L2R (TT / G2)        // 32 rows per coarse chunk
#define P2T 1024             // pass2 threads per block
#define SER2 (G2 / P2T)      // 4 coarse chunks serially per pass2 thread

#define CPB3 4               // coarse chunks per pass3 block (256 threads)

// Scratch (static device arrays — allocation rules). 16MB total, L2-resident.
__device__ float g_aggA[G2 * DD];    // [c2][d] chunk-major coarse aggregates
__device__ float g_aggS[G2 * DD];
__device__ float g_prefA[G2 * DD];   // [c2][d] exclusive prefixes
__device__ float g_prefS[G2 * DD];

// ---------------- pass 1: fine scan -> coarse aggregates ----------------
__global__ __launch_bounds__(V4 * CPB1, 6) void s5_pass1(const float4* __restrict__ A4,
                                                         const float4* __restrict__ Bu4) {
    __shared__ float4 shA[2][V4];
    __shared__ float4 shS[2][V4];

    const int sub = threadIdx.x >> 6;       // fine chunk within block (0..3)
    const int t   = threadIdx.x & 63;       // float4 lane (channels 4t..4t+3)
    const int c   = blockIdx.x * CPB1 + sub;
    const size_t base = (size_t)c * L1 * V4 + t;

    float4 aA = make_float4(1.f, 1.f, 1.f, 1.f);
    float4 s  = make_float4(0.f, 0.f, 0.f, 0.f);
#pragma unroll
    for (int i = 0; i < L1; ++i) {
        const float4 a  = A4[base + (size_t)i * V4];    // default caching: seed L2
        const float4 bu = Bu4[base + (size_t)i * V4];
        aA.x *= a.x; aA.y *= a.y; aA.z *= a.z; aA.w *= a.w;
        s.x = fmaf(a.x, s.x, bu.x);
        s.y = fmaf(a.y, s.y, bu.y);
        s.z = fmaf(a.z, s.z, bu.z);
        s.w = fmaf(a.w, s.w, bu.w);
    }

    // pair-combine fine chunks (sub0,sub1)->coarse0, (sub2,sub3)->coarse1
    if (sub & 1) {                          // odd sub = LATER fine chunk
        shA[sub >> 1][t] = aA;
        shS[sub >> 1][t] = s;
    }
    __syncthreads();
    if (!(sub & 1)) {                       // even sub = EARLIER fine chunk
        const float4 a1 = shA[sub >> 1][t];
        const float4 s1 = shS[sub >> 1][t];
        float4 cA, cS;                      // coarse = later(a1,s1) ∘ earlier(aA,s)
        cA.x = a1.x * aA.x; cA.y = a1.y * aA.y;
        cA.z = a1.z * aA.z; cA.w = a1.w * aA.w;
        cS.x = fmaf(a1.x, s.x, s1.x); cS.y = fmaf(a1.y, s.y, s1.y);
        cS.z = fmaf(a1.z, s.z, s1.z); cS.w = fmaf(a1.w, s.w, s1.w);
        const int c2 = blockIdx.x * 2 + (sub >> 1);
        ((float4*)g_aggA)[c2 * V4 + t] = cA;    // coalesced, stays in L2
        ((float4*)g_aggS)[c2 * V4 + t] = cS;
    }
}

// ---------------- pass 2: cross-chunk scan (one block per channel) ----------
__global__ __launch_bounds__(P2T) void s5_pass2() {
    __shared__ float shA[P2T];
    __shared__ float shS[P2T];
    const int d = blockIdx.x;
    const int c = threadIdx.x;              // owns coarse chunks 4c..4c+3

    float la[SER2], ls[SER2];
    float vA = 1.f, vS = 0.f;
#pragma unroll
    for (int j = 0; j < SER2; ++j) {
        const float a = g_aggA[(c * SER2 + j) * DD + d];
        const float s = g_aggS[(c * SER2 + j) * DD + d];
        la[j] = a; ls[j] = s;
        vS = fmaf(a, vS, s);
        vA = vA * a;
    }
    shA[c] = vA;
    shS[c] = vS;
    __syncthreads();

    // Kogge-Stone inclusive scan over 1024 thread-aggregates
#pragma unroll
    for (int off = 1; off < P2T; off <<= 1) {
        float pA = 0.f, pS = 0.f;
        const bool valid = (c >= off);
        if (valid) { pA = shA[c - off]; pS = shS[c - off]; }
        __syncthreads();
        if (valid) {
            vS = fmaf(vA, pS, vS);
            vA = vA * pA;
            shA[c] = vA;
            shS[c] = vS;
        }
        __syncthreads();
    }

    // exclusive prefix entering this thread's SER2 chunks
    float eA = (c == 0) ? 1.f : shA[c - 1];
    float eS = (c == 0) ? 0.f : shS[c - 1];
#pragma unroll
    for (int j = 0; j < SER2; ++j) {
        g_prefA[(c * SER2 + j) * DD + d] = eA;
        g_prefS[(c * SER2 + j) * DD + d] = eS;
        eS = fmaf(la[j], eS, ls[j]);
        eA = eA * la[j];
    }
}

// ---------------- pass 3: rescan coarse chunks, write outputs ---------------
// R9-exact config: 256-thread blocks, 4 coarse chunks each, 32-row bursts,
// REVERSE order to hit pass1's L2-resident input tail.
__global__ __launch_bounds__(V4 * CPB3) void s5_pass3(const float4* __restrict__ A4,
                                                      const float4* __restrict__ Bu4,
                                                      float4* __restrict__ outA4,
                                                      float4* __restrict__ outS4) {
    const int sub = threadIdx.x >> 6;       // coarse chunk within block (0..3)
    const int t   = threadIdx.x & 63;
    const int c2  = (G2 - 1) - (blockIdx.x * CPB3 + sub);   // reverse mapping
    const size_t base = (size_t)c2 * L2R * V4 + t;

    float4 aA = ((const float4*)g_prefA)[c2 * V4 + t];   // coalesced (L2 hit)
    float4 s  = ((const float4*)g_prefS)[c2 * V4 + t];

#pragma unroll
    for (int i = 0; i < L2R; ++i) {
        const size_t idx = base + (size_t)i * V4;
        const float4 a  = A4[idx];          // default caching: exploit L2 leftovers
        const float4 bu = Bu4[idx];
        aA.x *= a.x; aA.y *= a.y; aA.z *= a.z; aA.w *= a.w;
        s.x = fmaf(a.x, s.x, bu.x);
        s.y = fmaf(a.y, s.y, bu.y);
        s.z = fmaf(a.z, s.z, bu.z);
        s.w = fmaf(a.w, s.w, bu.w);
        __stcs(outA4 + idx, aA);            // streaming: don't evict inputs
        __stcs(outS4 + idx, s);
    }
}

extern "C" void kernel_launch(void* const* d_in, const int* in_sizes, int n_in,
                              void* d_out, int out_size) {
    const float4* A4  = (const float4*)d_in[0];
    const float4* Bu4 = (const float4*)d_in[1];
    float4* outA4 = (float4*)d_out;
    float4* outS4 = (float4*)((float*)d_out + (size_t)TT * DD);

    s5_pass1<<<G1 / CPB1, V4 * CPB1>>>(A4, Bu4);
    s5_pass2<<<DD, P2T>>>();
    s5_pass3<<<G2 / CPB3, V4 * CPB3>>>(A4, Bu4, outA4, outS4);
}